// round 12
// baseline (speedup 1.0000x reference)
#include <cuda_runtime.h>
#include <cstdint>

#define NB 128
#define NV 128000
#define KTOP 20
#define NTHREADS 1024
#define CAP 4096
#define THRESH 3.0f

#define NSTAGE 4
#define TILE_ELEMS 4000
#define TILE_VEC 1000
#define STAGE_BYTES 16000
#define NTILE 32            // NV / TILE_ELEMS

// dynamic smem layout (bytes)
#define L_OFF    0                       // 4 * 16000
#define U_OFF    64000                   // 4 * 16000
#define VAL_OFF  128000                  // float[CAP]
#define IDX_OFF  144384                  // int[CAP]
#define MB_OFF   160768                  // 4 mbarriers (u64)
#define WARP_OFF 160800                  // float[32]
#define GK_OFF   160928                  // u64
#define WIN_OFF  160936                  // u64
#define LSE_OFF  160944                  // float
#define CNT_OFF  160948                  // int
#define SELV_OFF 160952                  // float[KTOP]
#define SELI_OFF 161032                  // int[KTOP]
#define SMEM_TOTAL 161152

__device__ __forceinline__ float fast_ex2(float x) {
    float r; asm("ex2.approx.ftz.f32 %0, %1;" : "=f"(r) : "f"(x)); return r;
}
__device__ __forceinline__ float fast_lg2(float x) {
    float r; asm("lg2.approx.ftz.f32 %0, %1;" : "=f"(r) : "f"(x)); return r;
}
__device__ __forceinline__ uint32_t smem_u32(const void* p) {
    uint32_t a;
    asm("{ .reg .u64 t; cvta.to.shared.u64 t, %1; cvt.u32.u64 %0, t; }" : "=r"(a) : "l"(p));
    return a;
}
__device__ __forceinline__ void mbar_init(uint32_t addr, uint32_t count) {
    asm volatile("mbarrier.init.shared.b64 [%0], %1;" :: "r"(addr), "r"(count) : "memory");
}
__device__ __forceinline__ void mbar_expect_tx(uint32_t addr, uint32_t bytes) {
    asm volatile("mbarrier.arrive.expect_tx.shared.b64 _, [%0], %1;" :: "r"(addr), "r"(bytes) : "memory");
}
__device__ __forceinline__ void bulk_g2s(uint32_t dst, const void* src, uint32_t bytes, uint32_t mbar) {
    asm volatile("cp.async.bulk.shared::cta.global.mbarrier::complete_tx::bytes [%0], [%1], %2, [%3];"
                 :: "r"(dst), "l"(src), "r"(bytes), "r"(mbar) : "memory");
}
__device__ __forceinline__ void mbar_wait(uint32_t addr, uint32_t parity) {
    asm volatile(
        "{\n\t.reg .pred P;\n\t"
        "W_%=:\n\t"
        "mbarrier.try_wait.parity.acquire.cta.shared::cta.b64 P, [%0], %1;\n\t"
        "@!P bra W_%=;\n\t}"
        :: "r"(addr), "r"(parity) : "memory");
}

// Monotone pack: larger value wins; on equal value, SMALLER index wins (jax tie rule).
__device__ __forceinline__ unsigned long long packkey(float v, int idx) {
    unsigned fb = __float_as_uint(v);
    fb = (fb & 0x80000000u) ? ~fb : (fb | 0x80000000u);
    return ((unsigned long long)fb << 32) | (unsigned long long)(~(unsigned)idx);
}

// Accurate -ln(u) for u in (0,1): poly(log1p) near 1, MUFU lg2 elsewhere.
__device__ __forceinline__ float neg_log(float u) {
    float d = u - 1.0f;
    float p = fmaf(d, 0.2f, -0.25f);
    p = fmaf(d, p, 0.333333333f);
    p = fmaf(d, p, -0.5f);
    p = fmaf(d, p, 1.0f);
    float lp = -d * p;                        // -log1p(d), good for d in (-0.16, 0]
    float lm = -0.693147181f * fast_lg2(u);
    return (u > 0.84f) ? lp : lm;
}

__global__ __launch_bounds__(NTHREADS) void sampler_kernel(
    const float* __restrict__ logits,
    const float* __restrict__ temp,
    const float* __restrict__ u,
    float* __restrict__ out)
{
    extern __shared__ char sm[];
    const int b   = blockIdx.x;
    const int tid = threadIdx.x;

    float* s_val   = (float*)(sm + VAL_OFF);
    int*   s_idx   = (int*)(sm + IDX_OFF);
    float* s_warp  = (float*)(sm + WARP_OFF);
    unsigned long long* s_gkey = (unsigned long long*)(sm + GK_OFF);
    unsigned long long* s_win  = (unsigned long long*)(sm + WIN_OFF);
    float* s_lse   = (float*)(sm + LSE_OFF);
    int*   s_cnt   = (int*)(sm + CNT_OFF);
    float* s_selval = (float*)(sm + SELV_OFF);
    int*   s_selidx = (int*)(sm + SELI_OFF);

    const uint32_t mb0 = smem_u32(sm + MB_OFF);
    const uint32_t smL = smem_u32(sm + L_OFF);
    const uint32_t smU = smem_u32(sm + U_OFF);

    const float* lrow = logits + (size_t)b * NV;
    const float* urow = u      + (size_t)b * NV;

    if (tid == 0) {
        *s_cnt = 0; *s_gkey = 0ull;
        #pragma unroll
        for (int s = 0; s < NSTAGE; s++) mbar_init(mb0 + 8 * s, 1);
    }
    __syncthreads();

    // prologue: post all 4 stages
    if (tid == 0) {
        #pragma unroll
        for (int k = 0; k < NSTAGE; k++) {
            mbar_expect_tx(mb0 + 8 * k, 2 * STAGE_BYTES);
            bulk_g2s(smL + k * STAGE_BYTES, lrow + k * TILE_ELEMS, STAGE_BYTES, mb0 + 8 * k);
            bulk_g2s(smU + k * STAGE_BYTES, urow + k * TILE_ELEMS, STAGE_BYTES, mb0 + 8 * k);
        }
    }

    const float t      = temp[b];
    const bool  greedy = (t < 1e-5f);
    const float tt     = greedy ? 1.0f : t;
    const float inv_t  = 1.0f / tt;
    const float c      = inv_t * 1.44269504088896f;

    float acc0 = 0.0f, acc1 = 0.0f;
    float best_e  = 0.0f;
    float best_lq = 1.0f;
    int   best_gi = 0;
    float invK    = 1e30f;

    #define RARE(lv, uv, ee, gidx)                                                  \
    {                                                                               \
        if ((lv) > THRESH) {                                                        \
            int p = atomicAdd(s_cnt, 1);                                            \
            if (p < CAP) { s_val[p] = (lv); s_idx[p] = (gidx); }                    \
        }                                                                           \
        if (fmaf((ee), invK, (uv)) > 0.999f) {                                      \
            float lq = neg_log(uv);                                                 \
            if ((ee) * best_lq > best_e * lq) {                                     \
                best_e = (ee); best_lq = lq; best_gi = (gidx);                      \
                invK = 1.01f * (lq / (ee));                                         \
            }                                                                       \
        }                                                                           \
    }
    #define ELEM(lv, uv, ee, gidx)                                                  \
    {                                                                               \
        bool hot = ((lv) > THRESH) | (fmaf((ee), invK, (uv)) > 0.999f);             \
        if (hot) RARE(lv, uv, ee, gidx)                                             \
    }

    const float4* smL4 = (const float4*)(sm + L_OFF);
    const float4* smU4 = (const float4*)(sm + U_OFF);

    for (int k = 0; k < NTILE; k++) {
        const int s  = k & (NSTAGE - 1);
        const int ph = (k >> 2) & 1;
        mbar_wait(mb0 + 8 * s, ph);

        if (tid < TILE_VEC) {
            float4 L = smL4[s * TILE_VEC + tid];
            float4 U = smU4[s * TILE_VEC + tid];
            float e0 = fast_ex2(L.x * c), e1 = fast_ex2(L.y * c);
            float e2 = fast_ex2(L.z * c), e3 = fast_ex2(L.w * c);
            acc0 += (e0 + e1); acc1 += (e2 + e3);
            int g0 = k * TILE_ELEMS + 4 * tid;
            ELEM(L.x, U.x, e0, g0 + 0) ELEM(L.y, U.y, e1, g0 + 1)
            ELEM(L.z, U.z, e2, g0 + 2) ELEM(L.w, U.w, e3, g0 + 3)
        }
        __syncthreads();   // stage s fully consumed by every thread

        const int kk = k + NSTAGE;
        if (tid == 0 && kk < NTILE) {
            mbar_expect_tx(mb0 + 8 * s, 2 * STAGE_BYTES);
            bulk_g2s(smL + s * STAGE_BYTES, lrow + kk * TILE_ELEMS, STAGE_BYTES, mb0 + 8 * s);
            bulk_g2s(smU + s * STAGE_BYTES, urow + kk * TILE_ELEMS, STAGE_BYTES, mb0 + 8 * s);
        }
    }
    #undef ELEM
    #undef RARE

    // ---- sumexp reduction ----
    float sumexp = acc0 + acc1;
    #pragma unroll
    for (int o = 16; o; o >>= 1) sumexp += __shfl_down_sync(0xFFFFFFFFu, sumexp, o);
    if ((tid & 31) == 0) s_warp[tid >> 5] = sumexp;

    // ---- Gumbel winner across threads ----
    atomicMax(s_gkey, packkey(best_e / best_lq, best_gi));
    __syncthreads();

    if (tid == 0) {
        float s = 0.0f;
        #pragma unroll
        for (int w = 0; w < NTHREADS / 32; w++) s += s_warp[w];
        *s_lse = 0.693147181f * fast_lg2(s);
    }

    // ---- top-K: single-pass rank selection over shared candidates ----
    const int cnt = *s_cnt;
    const bool okc = (cnt >= KTOP) && (cnt <= CAP);
    if (okc) {
        for (int p = tid; p < cnt; p += NTHREADS) {
            float v = s_val[p]; int ix = s_idx[p];
            unsigned long long my = packkey(v, ix);
            int rank = 0;
            for (int j = 0; j < cnt; j++)
                rank += (packkey(s_val[j], s_idx[j]) > my) ? 1 : 0;
            if (rank < KTOP) { s_selval[rank] = v; s_selidx[rank] = ix; }
        }
    } else {
        // robust fallback: 20 rounds of global argmax with exclusion (statistically never)
        unsigned long long bound = 0xFFFFFFFFFFFFFFFFull;
        for (int r = 0; r < KTOP; r++) {
            __syncthreads();
            if (tid == 0) *s_win = 0ull;
            __syncthreads();
            unsigned long long loc = 0ull;
            for (int p = tid; p < NV; p += NTHREADS) {
                unsigned long long k = packkey(lrow[p], p);
                if (k < bound && k > loc) loc = k;
            }
            if (loc) atomicMax(s_win, loc);
            __syncthreads();
            unsigned long long w = *s_win;
            bound = w;
            if (tid == 0) {
                unsigned fb = (unsigned)(w >> 32);
                fb = (fb & 0x80000000u) ? (fb ^ 0x80000000u) : ~fb;
                s_selval[r] = __uint_as_float(fb);
                s_selidx[r] = (int)(~(unsigned)(w & 0xFFFFFFFFull));
            }
        }
    }
    __syncthreads();

    // ---- outputs: [sampled(NB) | topk_logprobs(NB*K) | topk_indices(NB*K)] ----
    if (tid < KTOP) {
        float lp = s_selval[tid] * inv_t - *s_lse;
        out[NB + b * KTOP + tid]             = lp;
        out[NB + NB * KTOP + b * KTOP + tid] = (float)s_selidx[tid];
    }
    if (tid == 0) {
        int gi = (int)(~(unsigned)(*s_gkey & 0xFFFFFFFFull));
        out[b] = (float)(greedy ? s_selidx[0] : gi);
    }
}

extern "C" void kernel_launch(void* const* d_in, const int* in_sizes, int n_in,
                              void* d_out, int out_size) {
    const float* logits = (const float*)d_in[0];
    const float* temp   = (const float*)d_in[1];
    const float* u      = (const float*)d_in[2];
    (void)in_sizes; (void)n_in; (void)out_size;
    cudaFuncSetAttribute(sampler_kernel, cudaFuncAttributeMaxDynamicSharedMemorySize, SMEM_TOTAL);
    sampler_kernel<<<NB, NTHREADS, SMEM_TOTAL>>>(logits, temp, u, (float*)d_out);
}